// round 17
// baseline (speedup 1.0000x reference)
#include <cuda_runtime.h>

#define NVEH 4096
#define NT 256
#define PAST 25
#define LEADLEN 280
#define NQUAD 1024
#define WPC 7
#define NCTA 147
#define NTHREADS 224

typedef unsigned long long ull;

// ---- shared memory layout (float offsets) ----
#define W1_OFF   0
#define B1_OFF   288
#define B2P_OFF  320
#define W2X_OFF  384      // float4 [ci*32+c] = {w0[c], w0[c+32], w1[c], w1[c+32]}
#define W2K2_OFF 4480     // float4 [cp*32+c] = {k2[2cp][c],k2[2cp][c+32],k2[2cp+1][c],k2[2cp+1][c+32]}
#define WD2X_OFF 6528     // ull2 [(q*6+jj)*32+c]
#define BD2_OFF  10368
#define WD1_OFF  10378
#define BD1_OFF  10388
#define XBUF_OFF 10392    // 14 sets * 27 * 8 = 3024
#define ST_OFF   13416    // pool1 staging: 14 sets * 13*32 ull = 11648 floats
#define RR_OFF   25064    // r-ring: 14 sets * 16 slots * 32 * ull2 = 28672 floats
#define SMEM_FLOATS 53736 // 214944 B

__device__ __forceinline__ ull ffma2(ull a, ull b, ull c) {
    ull d; asm("fma.rn.f32x2 %0, %1, %2, %3;" : "=l"(d) : "l"(a), "l"(b), "l"(c)); return d;
}
__device__ __forceinline__ ull addf32x2(ull a, ull b) {
    ull d; asm("add.rn.f32x2 %0, %1, %2;" : "=l"(d) : "l"(a), "l"(b)); return d;
}
__device__ __forceinline__ void unpk(ull v, float& lo, float& hi) {
    asm("mov.b64 {%0, %1}, %2;" : "=f"(lo), "=f"(hi) : "l"(v));
}
__device__ __forceinline__ ull pkdup(float x) {
    ull d; asm("mov.b64 %0, {%1, %1};" : "=l"(d) : "f"(x)); return d;
}
__device__ __forceinline__ ull pk2(float a, float b) {
    ull d; asm("mov.b64 %0, {%1, %2};" : "=l"(d) : "f"(a), "f"(b)); return d;
}

__global__ void __launch_bounds__(NTHREADS, 1)
rnncf_kernel(const float* __restrict__ lead, const float* __restrict__ cur,
             const float* __restrict__ w1g, const float* __restrict__ b1g,
             const float* __restrict__ w2g, const float* __restrict__ b2g,
             const float* __restrict__ wd2g, const float* __restrict__ bd2g,
             const float* __restrict__ wd1g, const float* __restrict__ bd1g,
             float* __restrict__ out)
{
    extern __shared__ float sm[];
    const int tid = threadIdx.x;

    // ---------- cooperative weight staging ----------
    for (int i = tid; i < 288; i += NTHREADS) sm[W1_OFF + i] = w1g[i];
    for (int i = tid; i < 32;  i += NTHREADS) sm[B1_OFF + i] = b1g[i];
    {
        float2* b2p_s = (float2*)(sm + B2P_OFF);
        for (int i = tid; i < 32; i += NTHREADS)
            b2p_s[i] = make_float2(b2g[i], b2g[i + 32]);
        float4* w2x_s = (float4*)(sm + W2X_OFF);
        for (int i = tid; i < 1024; i += NTHREADS) {
            int ci = i >> 5, c = i & 31;
            w2x_s[i] = make_float4(w2g[ci * 64 + c],        w2g[ci * 64 + c + 32],
                                   w2g[(32 + ci) * 64 + c], w2g[(32 + ci) * 64 + c + 32]);
        }
        float4* w2k2_s = (float4*)(sm + W2K2_OFF);
        for (int i = tid; i < 512; i += NTHREADS) {
            int cp = i >> 5, c = i & 31;
            w2k2_s[i] = make_float4(w2g[(64 + 2 * cp) * 64 + c],     w2g[(64 + 2 * cp) * 64 + c + 32],
                                    w2g[(64 + 2 * cp + 1) * 64 + c], w2g[(64 + 2 * cp + 1) * 64 + c + 32]);
        }
        float4* wdx_s = (float4*)(sm + WD2X_OFF);
        for (int i = tid; i < 960; i += NTHREADS) {
            int q = i / 192, r = i - q * 192;
            int jj = r >> 5, c = r & 31;
            int ii = jj * 64 + c;
            wdx_s[i] = make_float4(wd2g[ii * 10 + 2 * q],        wd2g[ii * 10 + 2 * q + 1],
                                   wd2g[(ii + 32) * 10 + 2 * q], wd2g[(ii + 32) * 10 + 2 * q + 1]);
        }
    }
    for (int i = tid; i < 10; i += NTHREADS) sm[BD2_OFF + i] = bd2g[i];
    for (int i = tid; i < 10; i += NTHREADS) sm[WD1_OFF + i] = wd1g[i];
    if (tid == 0) sm[BD1_OFF] = bd1g[0];
    for (int i = tid; i < 14 * 27 * 8; i += NTHREADS) sm[XBUF_OFF + i] = 0.0f;
    __syncthreads();

    const int wid = tid >> 5, lane = tid & 31;
    const int quad = blockIdx.x * WPC + wid;
    if (quad >= NQUAD) return;

    float* xbuf0 = sm + XBUF_OFF + (wid * 2 + 0) * (27 * 8);
    float* xbuf1 = sm + XBUF_OFF + (wid * 2 + 1) * (27 * 8);
    ull* st0 = (ull*)(sm + ST_OFF) + (wid * 2 + 0) * (13 * 32);
    ull* st1 = (ull*)(sm + ST_OFF) + (wid * 2 + 1) * (13 * 32);
    const ulonglong2* sv0 = (const ulonglong2*)st0;
    const ulonglong2* sv1 = (const ulonglong2*)st1;
    ulonglong2* rr0 = (ulonglong2*)(sm + RR_OFF) + (wid * 2 + 0) * (16 * 32);
    ulonglong2* rr1 = (ulonglong2*)(sm + RR_OFF) + (wid * 2 + 1) * (16 * 32);
    const float4* w2xf   = (const float4*)(sm + W2X_OFF);
    const float4* w2k2f4 = (const float4*)(sm + W2K2_OFF);
    const ulonglong2* wdx = (const ulonglong2*)(sm + WD2X_OFF);

    const float2* lead2base = (const float2*)lead + (size_t)(4 * quad) * LEADLEN;
    float2*       out2base  = (float2*)out + (size_t)(4 * quad) * NT;

    ull w1d[9];
    #pragma unroll
    for (int i = 0; i < 9; ++i) w1d[i] = pkdup(sm[W1_OFF + i * 32 + lane]);
    const ull b1d = pkdup(sm[B1_OFF + lane]);
    ull b2lo, b2hi;
    {
        float2 b2v = ((const float2*)(sm + B2P_OFF))[lane];
        b2lo = pkdup(b2v.x); b2hi = pkdup(b2v.y);
    }

    // ---------- initial windows: lane i (<25) holds column i, packed {A,B} ----------
    float2 xw0[2], xw1[2], xw2[2];
    #pragma unroll
    for (int s = 0; s < 2; ++s) {
        xw0[s] = make_float2(0.f, 0.f); xw1[s] = make_float2(0.f, 0.f); xw2[s] = make_float2(0.f, 0.f);
    }
    float p24v[4], s24v[4];
    {
        float tp[4] = {0.f,0.f,0.f,0.f}, ts[4] = {0.f,0.f,0.f,0.f};
        if (lane < PAST) {
            const float2* cur2base = (const float2*)cur + (size_t)(4 * quad) * PAST;
            #pragma unroll
            for (int i = 0; i < 4; ++i) {
                float2 cs = cur2base[i * PAST + lane];
                float2 ld = lead2base[i * LEADLEN + lane];
                float X0 = (ld.x - cs.x) * (1.0f / 200.0f);
                float X1 = cs.y * (1.0f / 40.0f);
                float X2 = ld.y * (1.0f / 40.0f);
                int s = i >> 1;
                if ((i & 1) == 0) { xw0[s].x = X0; xw1[s].x = X1; xw2[s].x = X2; }
                else              { xw0[s].y = X0; xw1[s].y = X1; xw2[s].y = X2; }
                tp[i] = cs.x; ts[i] = cs.y;
            }
        }
        #pragma unroll
        for (int i = 0; i < 4; ++i) {
            p24v[i] = __shfl_sync(0xffffffffu, tp[i], 24);
            s24v[i] = __shfl_sync(0xffffffffu, ts[i], 24);
        }
    }
    float2 ldnv[4];
    #pragma unroll
    for (int i = 0; i < 4; ++i) ldnv[i] = make_float2(0.f, 0.f);

    // fap/fbp arrays shared by seed+steady tails (captured by dense_tail)
    ull fapA0[6], fbpA0[6], fapB0[6], fbpB0[6];
    ull fapA1[6], fbpA1[6], fapB1[6], fbpB1[6];

    // ---------- helpers ----------
    auto c1p3 = [&](ulonglong2 a01, ull a2, ulonglong2 b01, ull b2_, ulonglong2 c01, ull c2) -> ull {
        ull h = b1d;
        h = ffma2(a01.x, w1d[0], h); h = ffma2(a01.y, w1d[1], h); h = ffma2(a2,  w1d[2], h);
        h = ffma2(b01.x, w1d[3], h); h = ffma2(b01.y, w1d[4], h); h = ffma2(b2_, w1d[5], h);
        h = ffma2(c01.x, w1d[6], h); h = ffma2(c01.y, w1d[7], h); h = ffma2(c2,  w1d[8], h);
        return h;
    };
    auto poolpair = [&](ull h0, ull h1) -> ull {
        float a, b, c, d;
        unpk(h0, a, b); unpk(h1, c, d);
        return pk2(fmaxf(fmaxf(a, 0.f), fmaxf(c, 0.f)), fmaxf(fmaxf(b, 0.f), fmaxf(d, 0.f)));
    };
    auto poolone = [&](ull h0) -> ull {
        float a, b; unpk(h0, a, b);
        return pk2(fmaxf(a, 0.f), fmaxf(b, 0.f));
    };

    auto publish_full = [&]() {
        if (lane < PAST) {
            *(float4*)(xbuf0 + (lane + 1) * 8)     = make_float4(xw0[0].x, xw0[0].y, xw1[0].x, xw1[0].y);
            *(float2*)(xbuf0 + (lane + 1) * 8 + 4) = xw2[0];
            *(float4*)(xbuf1 + (lane + 1) * 8)     = make_float4(xw0[1].x, xw0[1].y, xw1[1].x, xw1[1].y);
            *(float2*)(xbuf1 + (lane + 1) * 8 + 4) = xw2[1];
        }
        __syncwarp();
    };
    auto publish_part = [&]() {   // cols 0..6 and 17..24
        bool w = (lane < 7) || (lane >= 17 && lane < 25);
        if (w) {
            *(float4*)(xbuf0 + (lane + 1) * 8)     = make_float4(xw0[0].x, xw0[0].y, xw1[0].x, xw1[0].y);
            *(float2*)(xbuf0 + (lane + 1) * 8 + 4) = xw2[0];
            *(float4*)(xbuf1 + (lane + 1) * 8)     = make_float4(xw0[1].x, xw0[1].y, xw1[1].x, xw1[1].y);
            *(float2*)(xbuf1 + (lane + 1) * 8 + 4) = xw2[1];
        }
        __syncwarp();
    };

    auto conv1_full = [&](const float* xb, ull* st) {   // seeds: all 13 slots
        ulonglong2 a01 = *(const ulonglong2*)(xb);
        ull        a2  = *(const ull*)(xb + 4);
        ulonglong2 b01 = *(const ulonglong2*)(xb + 8);
        ull        b2_ = *(const ull*)(xb + 12);
        #pragma unroll
        for (int m = 0; m < 12; ++m) {
            ulonglong2 c01 = *(const ulonglong2*)(xb + (2 * m + 2) * 8);
            ull        c2  = *(const ull*)(xb + (2 * m + 2) * 8 + 4);
            ulonglong2 d01 = *(const ulonglong2*)(xb + (2 * m + 3) * 8);
            ull        d2  = *(const ull*)(xb + (2 * m + 3) * 8 + 4);
            st[m * 32 + lane] = poolpair(c1p3(a01, a2, b01, b2_, c01, c2),
                                         c1p3(b01, b2_, c01, c2, d01, d2));
            a01 = c01; a2 = c2; b01 = d01; b2_ = d2;
        }
        ulonglong2 c01 = *(const ulonglong2*)(xb + 26 * 8);
        ull        c2  = *(const ull*)(xb + 26 * 8 + 4);
        st[12 * 32 + lane] = poolone(c1p3(a01, a2, b01, b2_, c01, c2));
    };

    auto conv1_7 = [&](const float* xb, ull* st) {   // steady: slots 0..2 and 9..12
        ulonglong2 a01 = *(const ulonglong2*)(xb);
        ull        a2  = *(const ull*)(xb + 4);
        ulonglong2 b01 = *(const ulonglong2*)(xb + 8);
        ull        b2_ = *(const ull*)(xb + 12);
        #pragma unroll
        for (int m = 0; m < 3; ++m) {
            ulonglong2 c01 = *(const ulonglong2*)(xb + (2 * m + 2) * 8);
            ull        c2  = *(const ull*)(xb + (2 * m + 2) * 8 + 4);
            ulonglong2 d01 = *(const ulonglong2*)(xb + (2 * m + 3) * 8);
            ull        d2  = *(const ull*)(xb + (2 * m + 3) * 8 + 4);
            st[m * 32 + lane] = poolpair(c1p3(a01, a2, b01, b2_, c01, c2),
                                         c1p3(b01, b2_, c01, c2, d01, d2));
            a01 = c01; a2 = c2; b01 = d01; b2_ = d2;
        }
        a01 = *(const ulonglong2*)(xb + 18 * 8); a2  = *(const ull*)(xb + 18 * 8 + 4);
        b01 = *(const ulonglong2*)(xb + 19 * 8); b2_ = *(const ull*)(xb + 19 * 8 + 4);
        #pragma unroll
        for (int m = 9; m < 12; ++m) {
            ulonglong2 c01 = *(const ulonglong2*)(xb + (2 * m + 2) * 8);
            ull        c2  = *(const ull*)(xb + (2 * m + 2) * 8 + 4);
            ulonglong2 d01 = *(const ulonglong2*)(xb + (2 * m + 3) * 8);
            ull        d2  = *(const ull*)(xb + (2 * m + 3) * 8 + 4);
            st[m * 32 + lane] = poolpair(c1p3(a01, a2, b01, b2_, c01, c2),
                                         c1p3(b01, b2_, c01, c2, d01, d2));
            a01 = c01; a2 = c2; b01 = d01; b2_ = d2;
        }
        ulonglong2 c01 = *(const ulonglong2*)(xb + 26 * 8);
        ull        c2  = *(const ull*)(xb + 26 * 8 + 4);
        st[12 * 32 + lane] = poolone(c1p3(a01, a2, b01, b2_, c01, c2));
    };

    auto conv2_full = [&](const ulonglong2* q, ull* Lo, ull* Hi) {   // seeds
        #pragma unroll
        for (int j = 0; j < 11; ++j) { Lo[j] = b2lo; Hi[j] = b2hi; }
        #pragma unroll 1
        for (int cp = 0; cp < 16; ++cp) {
            float4 wa0 = w2xf[(2 * cp)     * 32 + lane];
            float4 wa1 = w2xf[(2 * cp + 1) * 32 + lane];
            float4 kk  = w2k2f4[cp * 32 + lane];
            ull d00 = pkdup(wa0.x), d01 = pkdup(wa0.y), d10 = pkdup(wa0.z), d11 = pkdup(wa0.w);
            ull e00 = pkdup(wa1.x), e01 = pkdup(wa1.y), e10 = pkdup(wa1.z), e11 = pkdup(wa1.w);
            ull d20 = pkdup(kk.x),  d21 = pkdup(kk.y),  e20 = pkdup(kk.z),  e21 = pkdup(kk.w);
            #pragma unroll
            for (int m = 0; m < 13; ++m) {
                ulonglong2 qp = q[m * 16 + cp];
                if (m <= 10) {
                    Lo[m] = ffma2(qp.x, d00, Lo[m]); Lo[m] = ffma2(qp.y, e00, Lo[m]);
                    Hi[m] = ffma2(qp.x, d01, Hi[m]); Hi[m] = ffma2(qp.y, e01, Hi[m]);
                }
                if (m >= 1 && m <= 11) {
                    Lo[m-1] = ffma2(qp.x, d10, Lo[m-1]); Lo[m-1] = ffma2(qp.y, e10, Lo[m-1]);
                    Hi[m-1] = ffma2(qp.x, d11, Hi[m-1]); Hi[m-1] = ffma2(qp.y, e11, Hi[m-1]);
                }
                if (m >= 2) {
                    Lo[m-2] = ffma2(qp.x, d20, Lo[m-2]); Lo[m-2] = ffma2(qp.y, e20, Lo[m-2]);
                    Hi[m-2] = ffma2(qp.x, d21, Hi[m-2]); Hi[m-2] = ffma2(qp.y, e21, Hi[m-2]);
                }
            }
        }
    };

    // steady: fresh conv2 positions {0,9,10}, both sets, fixed staging offsets
    auto conv2_inc2 = [&](ull (&nlo)[2][3], ull (&nhi)[2][3]) {
        #pragma unroll
        for (int s = 0; s < 2; ++s) {
            nlo[s][0] = nlo[s][1] = nlo[s][2] = b2lo;
            nhi[s][0] = nhi[s][1] = nhi[s][2] = b2hi;
        }
        #pragma unroll 4
        for (int cp = 0; cp < 16; ++cp) {
            float4 wa0 = w2xf[(2 * cp)     * 32 + lane];
            float4 wa1 = w2xf[(2 * cp + 1) * 32 + lane];
            float4 kk  = w2k2f4[cp * 32 + lane];
            ull d00 = pkdup(wa0.x), d01 = pkdup(wa0.y), d10 = pkdup(wa0.z), d11 = pkdup(wa0.w);
            ull e00 = pkdup(wa1.x), e01 = pkdup(wa1.y), e10 = pkdup(wa1.z), e11 = pkdup(wa1.w);
            ull d20 = pkdup(kk.x),  d21 = pkdup(kk.y),  e20 = pkdup(kk.z),  e21 = pkdup(kk.w);
            #pragma unroll
            for (int s = 0; s < 2; ++s) {
                const ulonglong2* q = s ? sv1 : sv0;
                ulonglong2 q0 = q[0 + cp], q1 = q[16 + cp], q2 = q[32 + cp];
                nlo[s][0] = ffma2(q0.x, d00, nlo[s][0]); nlo[s][0] = ffma2(q0.y, e00, nlo[s][0]);
                nhi[s][0] = ffma2(q0.x, d01, nhi[s][0]); nhi[s][0] = ffma2(q0.y, e01, nhi[s][0]);
                nlo[s][0] = ffma2(q1.x, d10, nlo[s][0]); nlo[s][0] = ffma2(q1.y, e10, nlo[s][0]);
                nhi[s][0] = ffma2(q1.x, d11, nhi[s][0]); nhi[s][0] = ffma2(q1.y, e11, nhi[s][0]);
                nlo[s][0] = ffma2(q2.x, d20, nlo[s][0]); nlo[s][0] = ffma2(q2.y, e20, nlo[s][0]);
                nhi[s][0] = ffma2(q2.x, d21, nhi[s][0]); nhi[s][0] = ffma2(q2.y, e21, nhi[s][0]);

                ulonglong2 q9 = q[144 + cp], q10 = q[160 + cp], q11 = q[176 + cp], q12 = q[192 + cp];
                nlo[s][1] = ffma2(q9.x,  d00, nlo[s][1]); nlo[s][1] = ffma2(q9.y,  e00, nlo[s][1]);
                nhi[s][1] = ffma2(q9.x,  d01, nhi[s][1]); nhi[s][1] = ffma2(q9.y,  e01, nhi[s][1]);
                nlo[s][1] = ffma2(q10.x, d10, nlo[s][1]); nlo[s][1] = ffma2(q10.y, e10, nlo[s][1]);
                nhi[s][1] = ffma2(q10.x, d11, nhi[s][1]); nhi[s][1] = ffma2(q10.y, e11, nhi[s][1]);
                nlo[s][1] = ffma2(q11.x, d20, nlo[s][1]); nlo[s][1] = ffma2(q11.y, e20, nlo[s][1]);
                nhi[s][1] = ffma2(q11.x, d21, nhi[s][1]); nhi[s][1] = ffma2(q11.y, e21, nhi[s][1]);

                nlo[s][2] = ffma2(q10.x, d00, nlo[s][2]); nlo[s][2] = ffma2(q10.y, e00, nlo[s][2]);
                nhi[s][2] = ffma2(q10.x, d01, nhi[s][2]); nhi[s][2] = ffma2(q10.y, e01, nhi[s][2]);
                nlo[s][2] = ffma2(q11.x, d10, nlo[s][2]); nlo[s][2] = ffma2(q11.y, e10, nlo[s][2]);
                nhi[s][2] = ffma2(q11.x, d11, nhi[s][2]); nhi[s][2] = ffma2(q11.y, e11, nhi[s][2]);
                nlo[s][2] = ffma2(q12.x, d20, nlo[s][2]); nlo[s][2] = ffma2(q12.y, e20, nlo[s][2]);
                nhi[s][2] = ffma2(q12.x, d21, nhi[s][2]); nhi[s][2] = ffma2(q12.y, e21, nhi[s][2]);
            }
        }
    };

    // dense2 + 4-way parity reduce + dense1 + recurrence + output + window shift
    auto dense_tail = [&](int t) {
        ull sA0[5] = {0,0,0,0,0}, sB0[5] = {0,0,0,0,0};
        ull sA1[5] = {0,0,0,0,0}, sB1[5] = {0,0,0,0,0};
        #pragma unroll
        for (int jj = 0; jj < 6; ++jj) {
            #pragma unroll
            for (int q = 0; q < 5; ++q) {
                ulonglong2 w = wdx[(q * 6 + jj) * 32 + lane];
                sA0[q] = ffma2(fapA0[jj], w.x, sA0[q]); sA0[q] = ffma2(fbpA0[jj], w.y, sA0[q]);
                sB0[q] = ffma2(fapB0[jj], w.x, sB0[q]); sB0[q] = ffma2(fbpB0[jj], w.y, sB0[q]);
                sA1[q] = ffma2(fapA1[jj], w.x, sA1[q]); sA1[q] = ffma2(fbpA1[jj], w.y, sA1[q]);
                sB1[q] = ffma2(fapB1[jj], w.x, sB1[q]); sB1[q] = ffma2(fbpB1[jj], w.y, sB1[q]);
            }
        }
        const bool bit0 = (lane & 1), bit1 = (lane & 2);
        ull r0[5], r1[5], s5[5];
        #pragma unroll
        for (int q = 0; q < 5; ++q) {
            ull z = bit0 ? sB0[q] : sA0[q];
            ull x = bit0 ? sA0[q] : sB0[q];
            r0[q] = addf32x2(z, __shfl_xor_sync(0xffffffffu, x, 1));
            z = bit0 ? sB1[q] : sA1[q];
            x = bit0 ? sA1[q] : sB1[q];
            r1[q] = addf32x2(z, __shfl_xor_sync(0xffffffffu, x, 1));
        }
        #pragma unroll
        for (int q = 0; q < 5; ++q) {
            ull z = bit1 ? r1[q] : r0[q];
            ull x = bit1 ? r0[q] : r1[q];
            s5[q] = addf32x2(z, __shfl_xor_sync(0xffffffffu, x, 2));
        }
        #pragma unroll
        for (int off = 4; off <= 16; off <<= 1) {
            #pragma unroll
            for (int q = 0; q < 5; ++q)
                s5[q] = addf32x2(s5[q], __shfl_xor_sync(0xffffffffu, s5[q], off));
        }
        float d[10];
        #pragma unroll
        for (int q = 0; q < 5; ++q) unpk(s5[q], d[2 * q], d[2 * q + 1]);
        float y = sm[BD1_OFF];
        #pragma unroll
        for (int o = 0; o < 10; ++o)
            y = fmaf(fmaxf(d[o] + sm[BD2_OFF + o], 0.0f), sm[WD1_OFF + o], y);
        float accv = fmaf(10.0f, y, -6.0f);
        float av[4];
        #pragma unroll
        for (int i = 0; i < 4; ++i) av[i] = __shfl_sync(0xffffffffu, accv, i);

        float pp[4], ps[4];
        #pragma unroll
        for (int i = 0; i < 4; ++i) {
            pp[i] = fmaf(0.1f, s24v[i], p24v[i]);
            ps[i] = fmaf(0.1f, av[i],   s24v[i]);
            p24v[i] = pp[i]; s24v[i] = ps[i];
        }
        if (lane < 4) out2base[lane * NT + t] = make_float2(pp[lane], ps[lane]);

        #pragma unroll
        for (int s = 0; s < 2; ++s) {
            xw0[s].x = __shfl_down_sync(0xffffffffu, xw0[s].x, 1);
            xw0[s].y = __shfl_down_sync(0xffffffffu, xw0[s].y, 1);
            xw1[s].x = __shfl_down_sync(0xffffffffu, xw1[s].x, 1);
            xw1[s].y = __shfl_down_sync(0xffffffffu, xw1[s].y, 1);
            xw2[s].x = __shfl_down_sync(0xffffffffu, xw2[s].x, 1);
            xw2[s].y = __shfl_down_sync(0xffffffffu, xw2[s].y, 1);
            if (lane == 24) {
                int iA = 2 * s, iB = 2 * s + 1;
                xw0[s] = make_float2((ldnv[iA].x - pp[iA]) * (1.0f / 200.0f),
                                     (ldnv[iB].x - pp[iB]) * (1.0f / 200.0f));
                xw1[s] = make_float2(ps[iA] * (1.0f / 40.0f), ps[iB] * (1.0f / 40.0f));
                xw2[s] = make_float2(ldnv[iA].y * (1.0f / 40.0f), ldnv[iB].y * (1.0f / 40.0f));
            }
        }
    };

    // seed fap fill from full conv2 (one set); also records r_t into the ring
    auto seed_fill = [&](const ull* Lo, const ull* Hi, ulonglong2* rr, int t,
                         ull* fapA, ull* fbpA, ull* fapB, ull* fbpB) {
        #pragma unroll
        for (int jj = 0; jj < 5; ++jj) {
            float aA, aB, bA, bB;
            unpk(Lo[2 * jj], aA, aB); unpk(Lo[2 * jj + 1], bA, bB);
            fapA[jj] = pkdup(fmaxf(fmaxf(aA, 0.f), fmaxf(bA, 0.f)));
            fapB[jj] = pkdup(fmaxf(fmaxf(aB, 0.f), fmaxf(bB, 0.f)));
            unpk(Hi[2 * jj], aA, aB); unpk(Hi[2 * jj + 1], bA, bB);
            fbpA[jj] = pkdup(fmaxf(fmaxf(aA, 0.f), fmaxf(bA, 0.f)));
            fbpB[jj] = pkdup(fmaxf(fmaxf(aB, 0.f), fmaxf(bB, 0.f)));
        }
        float aA, aB;
        unpk(Lo[10], aA, aB);
        fapA[5] = pkdup(fmaxf(aA, 0.f)); fapB[5] = pkdup(fmaxf(aB, 0.f));
        unpk(Hi[10], aA, aB);
        fbpA[5] = pkdup(fmaxf(aA, 0.f)); fbpB[5] = pkdup(fmaxf(aB, 0.f));
        // record r_t = relu(conv2[9])
        float cA, cB, dA, dB;
        unpk(Lo[9], cA, cB); unpk(Hi[9], dA, dB);
        ulonglong2 rv;
        rv.x = pk2(fmaxf(cA, 0.f), fmaxf(cB, 0.f));
        rv.y = pk2(fmaxf(dA, 0.f), fmaxf(dB, 0.f));
        rr[(t & 15) * 32 + lane] = rv;
    };

    // steady fap fill from n0/n9/n10 + r-ring (one set)
    auto steady_fill = [&](ull n0lo, ull n0hi, ull n9lo, ull n9hi, ull nXlo, ull nXhi,
                           ulonglong2* rr, int t,
                           ull* fapA, ull* fbpA, ull* fapB, ull* fbpB) {
        int i16 = ((t - 16) & 15) * 32 + lane;
        int i14 = ((t - 14) & 15) * 32 + lane;
        int i12 = ((t - 12) & 15) * 32 + lane;
        int i10 = ((t - 10) & 15) * 32 + lane;
        int i8  = ((t - 8)  & 15) * 32 + lane;
        int i6  = ((t - 6)  & 15) * 32 + lane;
        int i4  = ((t - 4)  & 15) * 32 + lane;
        int i2  = ((t - 2)  & 15) * 32 + lane;
        ulonglong2 e16 = rr[i16];
        float aA, aB, bA, bB;
        // jj0 = max(relu n0, r_{t-16})
        unpk(n0lo, aA, aB); unpk(e16.x, bA, bB);
        fapA[0] = pkdup(fmaxf(fmaxf(aA, 0.f), bA));
        fapB[0] = pkdup(fmaxf(fmaxf(aB, 0.f), bB));
        unpk(n0hi, aA, aB); unpk(e16.y, bA, bB);
        fbpA[0] = pkdup(fmaxf(fmaxf(aA, 0.f), bA));
        fbpB[0] = pkdup(fmaxf(fmaxf(aB, 0.f), bB));
        // jj1..3 from ring pairs
        ulonglong2 ea = rr[i14], eb = rr[i12];
        unpk(ea.x, aA, aB); unpk(eb.x, bA, bB);
        fapA[1] = pkdup(fmaxf(aA, bA)); fapB[1] = pkdup(fmaxf(aB, bB));
        unpk(ea.y, aA, aB); unpk(eb.y, bA, bB);
        fbpA[1] = pkdup(fmaxf(aA, bA)); fbpB[1] = pkdup(fmaxf(aB, bB));
        ea = rr[i10]; eb = rr[i8];
        unpk(ea.x, aA, aB); unpk(eb.x, bA, bB);
        fapA[2] = pkdup(fmaxf(aA, bA)); fapB[2] = pkdup(fmaxf(aB, bB));
        unpk(ea.y, aA, aB); unpk(eb.y, bA, bB);
        fbpA[2] = pkdup(fmaxf(aA, bA)); fbpB[2] = pkdup(fmaxf(aB, bB));
        ea = rr[i6]; eb = rr[i4];
        unpk(ea.x, aA, aB); unpk(eb.x, bA, bB);
        fapA[3] = pkdup(fmaxf(aA, bA)); fapB[3] = pkdup(fmaxf(aB, bB));
        unpk(ea.y, aA, aB); unpk(eb.y, bA, bB);
        fbpA[3] = pkdup(fmaxf(aA, bA)); fbpB[3] = pkdup(fmaxf(aB, bB));
        // jj4 = max(r_{t-2}, relu n9); also build and store r_t
        ulonglong2 rv;
        {
            float cA, cB, dA, dB;
            unpk(n9lo, cA, cB); unpk(n9hi, dA, dB);
            float rlA = fmaxf(cA, 0.f), rlB = fmaxf(cB, 0.f);
            float rhA = fmaxf(dA, 0.f), rhB = fmaxf(dB, 0.f);
            rv.x = pk2(rlA, rlB); rv.y = pk2(rhA, rhB);
            ea = rr[i2];
            unpk(ea.x, aA, aB);
            fapA[4] = pkdup(fmaxf(aA, rlA)); fapB[4] = pkdup(fmaxf(aB, rlB));
            unpk(ea.y, aA, aB);
            fbpA[4] = pkdup(fmaxf(aA, rhA)); fbpB[4] = pkdup(fmaxf(aB, rhB));
        }
        rr[(t & 15) * 32 + lane] = rv;   // same slot as i16, read already done
        // jj5 = relu n10
        unpk(nXlo, aA, aB);
        fapA[5] = pkdup(fmaxf(aA, 0.f)); fapB[5] = pkdup(fmaxf(aB, 0.f));
        unpk(nXhi, aA, aB);
        fbpA[5] = pkdup(fmaxf(aA, 0.f)); fbpB[5] = pkdup(fmaxf(aB, 0.f));
    };

    // ---------- seed steps t = 0..15 : full compute, fill the r-ring ----------
    #pragma unroll 1
    for (int t = 0; t < 16; ++t) {
        if (lane == 24) {
            #pragma unroll
            for (int i = 0; i < 4; ++i) ldnv[i] = lead2base[i * LEADLEN + t + PAST];
        }
        publish_full();
        conv1_full(xbuf0, st0); conv1_full(xbuf1, st1);
        __syncwarp();
        ull Lo[11], Hi[11];
        conv2_full(sv0, Lo, Hi);
        seed_fill(Lo, Hi, rr0, t, fapA0, fbpA0, fapB0, fbpB0);
        conv2_full(sv1, Lo, Hi);
        seed_fill(Lo, Hi, rr1, t, fapA1, fbpA1, fapB1, fbpB1);
        dense_tail(t);
    }

    // ---------- steady loop t = 16..255 : uniform incremental body ----------
    #pragma unroll 1
    for (int t = 16; t < NT; ++t) {
        if (lane == 24 && t < NT - 1) {
            #pragma unroll
            for (int i = 0; i < 4; ++i) ldnv[i] = lead2base[i * LEADLEN + t + PAST];
        }
        publish_part();
        conv1_7(xbuf0, st0); conv1_7(xbuf1, st1);
        __syncwarp();
        ull nlo[2][3], nhi[2][3];
        conv2_inc2(nlo, nhi);
        steady_fill(nlo[0][0], nhi[0][0], nlo[0][1], nhi[0][1], nlo[0][2], nhi[0][2],
                    rr0, t, fapA0, fbpA0, fapB0, fbpB0);
        steady_fill(nlo[1][0], nhi[1][0], nlo[1][1], nhi[1][1], nlo[1][2], nhi[1][2],
                    rr1, t, fapA1, fbpA1, fapB1, fbpB1);
        dense_tail(t);
    }
}

extern "C" void kernel_launch(void* const* d_in, const int* in_sizes, int n_in,
                              void* d_out, int out_size)
{
    const float* lead = (const float*)d_in[0];   // (4096, 280, 2)
    const float* cur  = (const float*)d_in[1];   // (4096, 25, 2)
    // d_in[2] = mask (unused by the reference computation)
    const float* w1  = (const float*)d_in[3];
    const float* b1  = (const float*)d_in[4];
    const float* w2  = (const float*)d_in[5];
    const float* b2  = (const float*)d_in[6];
    const float* wd2 = (const float*)d_in[7];
    const float* bd2 = (const float*)d_in[8];
    const float* wd1 = (const float*)d_in[9];
    const float* bd1 = (const float*)d_in[10];
    float* out = (float*)d_out;                   // (4096, 256, 2)

    (void)in_sizes; (void)n_in; (void)out_size;

    size_t smem_bytes = (size_t)SMEM_FLOATS * sizeof(float);   // 214944 B
    cudaFuncSetAttribute(rnncf_kernel,
                         cudaFuncAttributeMaxDynamicSharedMemorySize,
                         (int)smem_bytes);
    rnncf_kernel<<<NCTA, NTHREADS, smem_bytes>>>(
        lead, cur, w1, b1, w2, b2, wd2, bd2, wd1, bd1, out);
}